// round 1
// baseline (speedup 1.0000x reference)
#include <cuda_runtime.h>
#include <cuda_bf16.h>
#include <math_constants.h>

#define NROW 32768      // B*H*W = 32*32*32
#define CDIM 256
#define NE   1024
#define BM   64
#define BN   64
#define BK   32
#define NTILE (NE/BN)        // 16
#define NCHUNK (CDIM/BK)     // 8
#define GTOT (NTILE*NCHUNK)  // 128
#define NBLK (NROW/BM)       // 512

// scratch (allocation-free rule: __device__ globals)
__device__ float  g_zkm[(size_t)CDIM * NROW];   // z transposed: [c][n], n=b*1024+hw
__device__ float  g_embT[(size_t)CDIM * NE];    // embeddings transposed: [k][j]
__device__ float  g_sz[NROW];
__device__ float  g_se[NE];
__device__ double g_partial[NBLK];

// ---------------- z transpose: (b,c,hw) -> zkm[c][b*1024+hw] ----------------
__global__ void zt_kernel(const float4* __restrict__ z4) {
    int i4 = blockIdx.x * 256 + threadIdx.x;   // 2,097,152 float4 exactly
    int hw4 = i4 & 255;
    int c   = (i4 >> 8) & 255;
    int b   = i4 >> 16;
    ((float4*)g_zkm)[((c << 5) + b) * 256 + hw4] = z4[i4];
}

// ---------------- emb transpose: emb[j][k] -> embT[k][j] ----------------
__global__ void et_kernel(const float* __restrict__ e) {
    int i = blockIdx.x * 256 + threadIdx.x;    // 262144
    int j = i & 1023, k = i >> 10;
    g_embT[i] = e[j * 256 + k];
}

// ---------------- per-code squared norms ----------------
__global__ void se_kernel(const float* __restrict__ e) {
    int j = blockIdx.x;
    float4 v = *(const float4*)&e[j * 256 + threadIdx.x * 4];
    float s = __fadd_rn(__fadd_rn(__fmul_rn(v.x,v.x), __fmul_rn(v.y,v.y)),
                        __fadd_rn(__fmul_rn(v.z,v.z), __fmul_rn(v.w,v.w)));
    for (int off = 16; off; off >>= 1) s += __shfl_down_sync(0xffffffffu, s, off);
    __shared__ float r2[2];
    if ((threadIdx.x & 31) == 0) r2[threadIdx.x >> 5] = s;
    __syncthreads();
    if (threadIdx.x == 0) g_se[j] = __fadd_rn(r2[0], r2[1]);
}

// ---------------- per-row squared norms (from zkm, coalesced) ----------------
__global__ void sz_kernel() {
    int n = blockIdx.x * 32 + threadIdx.x;
    float s = 0.f;
    for (int c = threadIdx.y; c < CDIM; c += 8) {
        float v = g_zkm[(size_t)c * NROW + n];
        s = __fadd_rn(s, __fmul_rn(v, v));
    }
    __shared__ float red[8][32];
    red[threadIdx.y][threadIdx.x] = s;
    __syncthreads();
    if (threadIdx.y == 0) {
        float t = red[0][threadIdx.x];
        #pragma unroll
        for (int y = 1; y < 8; y++) t = __fadd_rn(t, red[y][threadIdx.x]);
        g_sz[n] = t;
    }
}

// ---------------- fused distance + argmin + per-block loss partial ----------------
__global__ void __launch_bounds__(256, 2) vq_main_kernel(float* __restrict__ out) {
    extern __shared__ float sm[];
    float (*As)[BM] = (float(*)[BM])sm;                 // [256][64]  64KB
    float (*Bs)[BN] = (float(*)[BN])(sm + CDIM * BM);   // [32][64]   8KB

    const int tid  = threadIdx.x;
    const int tx   = tid & 15;
    const int ty   = tid >> 4;
    const int row0 = blockIdx.x * BM;

    // load full A tile (k-major) : As[k][r] = zkm[k][row0+r]
    #pragma unroll
    for (int q = 0; q < 16; ++q) {
        int f = tid + q * 256;          // 0..4095
        int k = f >> 4, j4 = f & 15;
        float4 v = *(const float4*)&g_zkm[(size_t)k * NROW + row0 + j4 * 4];
        *(float4*)&As[k][j4 * 4] = v;
    }

    float szr[4];
    #pragma unroll
    for (int i = 0; i < 4; i++) szr[i] = g_sz[row0 + ty * 4 + i];

    float bd[4]; int bi[4];
    #pragma unroll
    for (int i = 0; i < 4; i++) { bd[i] = CUDART_INF_F; bi[i] = 0; }

    // prefetch B chunk 0 into registers
    const int k0 = tid >> 4,          j0 = tid & 15;
    const int k1 = (tid + 256) >> 4,  j1 = (tid + 256) & 15;
    float4 p0 = *(const float4*)&g_embT[(size_t)k0 * NE + j0 * 4];
    float4 p1 = *(const float4*)&g_embT[(size_t)k1 * NE + j1 * 4];

    float acc[4][4];

    for (int g = 0; g < GTOT; ++g) {
        __syncthreads();                       // prior chunk's readers done
        *(float4*)&Bs[k0][j0 * 4] = p0;
        *(float4*)&Bs[k1][j1 * 4] = p1;
        if (g + 1 < GTOT) {
            int gn = g + 1, tile = gn >> 3, kc = gn & 7;
            p0 = *(const float4*)&g_embT[(size_t)(kc * BK + k0) * NE + tile * BN + j0 * 4];
            p1 = *(const float4*)&g_embT[(size_t)(kc * BK + k1) * NE + tile * BN + j1 * 4];
        }
        __syncthreads();                       // Bs (and on g==0, As) visible

        const int kc = g & 7, tile = g >> 3;
        if (kc == 0) {
            #pragma unroll
            for (int i = 0; i < 4; i++)
                #pragma unroll
                for (int j = 0; j < 4; j++) acc[i][j] = 0.f;
        }
        const int kbase = kc * BK;
        #pragma unroll
        for (int k = 0; k < BK; ++k) {
            float4 a = *(const float4*)&As[kbase + k][ty * 4];
            float4 b = *(const float4*)&Bs[k][tx * 4];
            acc[0][0] = fmaf(a.x, b.x, acc[0][0]);
            acc[0][1] = fmaf(a.x, b.y, acc[0][1]);
            acc[0][2] = fmaf(a.x, b.z, acc[0][2]);
            acc[0][3] = fmaf(a.x, b.w, acc[0][3]);
            acc[1][0] = fmaf(a.y, b.x, acc[1][0]);
            acc[1][1] = fmaf(a.y, b.y, acc[1][1]);
            acc[1][2] = fmaf(a.y, b.z, acc[1][2]);
            acc[1][3] = fmaf(a.y, b.w, acc[1][3]);
            acc[2][0] = fmaf(a.z, b.x, acc[2][0]);
            acc[2][1] = fmaf(a.z, b.y, acc[2][1]);
            acc[2][2] = fmaf(a.z, b.z, acc[2][2]);
            acc[2][3] = fmaf(a.z, b.w, acc[2][3]);
            acc[3][0] = fmaf(a.w, b.x, acc[3][0]);
            acc[3][1] = fmaf(a.w, b.y, acc[3][1]);
            acc[3][2] = fmaf(a.w, b.z, acc[3][2]);
            acc[3][3] = fmaf(a.w, b.w, acc[3][3]);
        }
        if (kc == 7) {
            // d = fl( fl(sz+se) - 2*dot )  -- matches jax (A+B) - 2*matmul rounding
            #pragma unroll
            for (int j = 0; j < 4; j++) {
                int code = tile * BN + tx * 4 + j;
                float sej = g_se[code];
                #pragma unroll
                for (int i = 0; i < 4; i++) {
                    float t = __fadd_rn(szr[i], sej);
                    float d = fmaf(-2.0f, acc[i][j], t);
                    if (d < bd[i] || (d == bd[i] && code < bi[i])) { bd[i] = d; bi[i] = code; }
                }
            }
        }
    }

    // cross-thread argmin reduction (16 tx groups per row), lowest-index tie-break
    __syncthreads();
    float* red_d = (float*)Bs;            // 1024 floats
    int*   red_i = (int*)(red_d + 1024);  // 1024 ints  (== Bs 8KB exactly)
    #pragma unroll
    for (int i = 0; i < 4; i++) {
        int r = ty * 4 + i;
        red_d[r * 16 + tx] = bd[i];
        red_i[r * 16 + tx] = bi[i];
    }
    __syncthreads();
    double* rowsum = (double*)As;         // reuse A tile space
    if (tid < BM) {
        float best = red_d[tid * 16]; int bidx = red_i[tid * 16];
        #pragma unroll
        for (int t = 1; t < 16; t++) {
            float d = red_d[tid * 16 + t]; int c = red_i[tid * 16 + t];
            if (d < best || (d == best && c < bidx)) { best = d; bidx = c; }
        }
        out[row0 + tid] = (float)bidx;
        rowsum[tid] = (double)best;       // d_min == sum_c (z_q - z)^2 for this row
    }
    __syncthreads();
    if (tid < 32) {
        double s = rowsum[tid] + rowsum[tid + 32];
        for (int off = 16; off; off >>= 1)
            s += __shfl_down_sync(0xffffffffu, s, off);
        if (tid == 0) g_partial[blockIdx.x] = s;
    }
}

// ---------------- deterministic loss finalize ----------------
__global__ void loss_kernel(float* __restrict__ out, int out_size) {
    __shared__ double s[256];
    s[threadIdx.x] = g_partial[threadIdx.x] + g_partial[threadIdx.x + 256];
    __syncthreads();
    for (int off = 128; off; off >>= 1) {
        if (threadIdx.x < off) s[threadIdx.x] += s[threadIdx.x + off];
        __syncthreads();
    }
    if (threadIdx.x == 0 && out_size > NROW) {
        float m = (float)(s[0] / (double)((size_t)NROW * CDIM));
        out[NROW] = m + 0.25f * m;   // mean((sg(zq)-z)^2) + BETA*mean((zq-sg(z))^2)
    }
}

extern "C" void kernel_launch(void* const* d_in, const int* in_sizes, int n_in,
                              void* d_out, int out_size) {
    const float* z   = (const float*)d_in[0];   // (32,256,32,32) fp32
    const float* emb = (const float*)d_in[1];   // (1024,256)     fp32
    float* out = (float*)d_out;

    zt_kernel<<<8192, 256>>>((const float4*)z);
    et_kernel<<<1024, 256>>>(emb);
    se_kernel<<<1024, 64>>>(emb);
    sz_kernel<<<1024, dim3(32, 8)>>>();

    const int smem_bytes = (CDIM * BM + BK * BN) * (int)sizeof(float);  // 73728
    cudaFuncSetAttribute(vq_main_kernel, cudaFuncAttributeMaxDynamicSharedMemorySize, smem_bytes);
    vq_main_kernel<<<NBLK, 256, smem_bytes>>>(out);

    loss_kernel<<<1, 256>>>(out, out_size);
}